// round 7
// baseline (speedup 1.0000x reference)
#include <cuda_runtime.h>

#define POOLK 7
#define NBINS (POOLK * POOLK)
#define NUM_ROIS 300
#define FH 50
#define FW 50
#define FC 512

// Scratch (no cudaMalloc allowed)
__device__ float g_fmax[FH * FW];

// Block-wide max of 128 per-thread values (128 threads = 4 warps).
__device__ __forceinline__ float block_max_128(float m, float* smem,
                                               int tid) {
#pragma unroll
    for (int off = 16; off > 0; off >>= 1)
        m = fmaxf(m, __shfl_xor_sync(0xffffffffu, m, off));
    if ((tid & 31) == 0) smem[tid >> 5] = m;
    __syncthreads();
    // every thread folds the 4 warp results (no second sync needed before use)
    return fmaxf(fmaxf(smem[0], smem[1]), fmaxf(smem[2], smem[3]));
}

// K1: one BLOCK (128 threads) per pixel; each thread loads one float4 of the
// 512 channels. 2500 blocks = 10000 warps -> latency fully hidden.
__global__ void fmax_kernel(const float* __restrict__ fm) {
    __shared__ float smem[4];
    int pix = blockIdx.x;
    int tid = threadIdx.x;
    float4 v = reinterpret_cast<const float4*>(fm + (size_t)pix * FC)[tid];
    float m = fmaxf(fmaxf(v.x, v.y), fmaxf(v.z, v.w));
    m = block_max_128(m, smem, tid);
    if (tid == 0) g_fmax[pix] = m;
}

// K2: one BLOCK (128 threads) per (roi, bin). Bin region is at most 8x8=64
// pixels, so one L2 load per thread covers it; block-reduce; then each thread
// writes one float4 of the bin's 2KB output slab (perfectly coalesced).
__global__ void roi_kernel(const float* __restrict__ rois,
                           float* __restrict__ out) {
    __shared__ float smem[4];
    int idx = blockIdx.x;               // (roi, bin)
    int tid = threadIdx.x;

    int r = idx / NBINS;
    int bin = idx - r * NBINS;
    int i = bin / POOLK;
    int j = bin - i * POOLK;

    const float* roi = rois + r * 5;
    // reference: (rois * (1/16)).astype(int32) -> truncation; inputs >= 0
    int x1 = (int)(__ldg(roi + 1) * 0.0625f);
    int y1 = (int)(__ldg(roi + 2) * 0.0625f);
    int x2 = (int)(__ldg(roi + 3) * 0.0625f);
    int y2 = (int)(__ldg(roi + 4) * 0.0625f);
    int rh = y2 - y1 + 1;
    int rw = x2 - x1 + 1;

    int hs = min(max(y1 + (i * rh) / POOLK, 0), FH);
    int he = min(max(y1 + ((i + 1) * rh + POOLK - 1) / POOLK, 0), FH);
    int ws = min(max(x1 + (j * rw) / POOLK, 0), FW);
    int we = min(max(x1 + ((j + 1) * rw + POOLK - 1) / POOLK, 0), FW);

    int nh = he - hs;
    int nw = we - ws;
    int n = nh * nw;                    // <= 64 for these shapes

    float m = -INFINITY;
    if (tid < n) {
        int dy = tid / nw;
        int dx = tid - dy * nw;
        m = __ldg(g_fmax + (hs + dy) * FW + (ws + dx));
    }
    m = block_max_128(m, smem, tid);

    // write 512 floats = 128 float4, one per thread
    reinterpret_cast<float4*>(out + (size_t)idx * FC)[tid] =
        make_float4(m, m, m, m);
}

extern "C" void kernel_launch(void* const* d_in, const int* in_sizes, int n_in,
                              void* d_out, int out_size) {
    const float* rois = (const float*)d_in[0];          // (300, 5)
    const float* feature_maps = (const float*)d_in[1];  // (50, 50, 512)
    float* out = (float*)d_out;                         // (300, 7, 7, 512)

    fmax_kernel<<<FH * FW, 128>>>(feature_maps);
    roi_kernel<<<NUM_ROIS * NBINS, 128>>>(rois, out);
}

// round 8
// speedup vs baseline: 1.3096x; 1.3096x over previous
#include <cuda_runtime.h>

#define POOLK 7
#define NBINS (POOLK * POOLK)
#define NUM_ROIS 300
#define FH 50
#define FW 50
#define FC 512
#define BINS_PER_BLK 12   // 14700 / 12 = 1225 blocks exactly

// Scratch (no cudaMalloc allowed)
__device__ float g_fmax[FH * FW];

// K1: one BLOCK (128 threads) per pixel; each thread loads one float4 of the
// 512 channels, block-reduce. 2500 blocks -> latency fully hidden.
__global__ void fmax_kernel(const float* __restrict__ fm) {
    __shared__ float smem[4];
    int pix = blockIdx.x;
    int tid = threadIdx.x;
    float4 v = reinterpret_cast<const float4*>(fm + (size_t)pix * FC)[tid];
    float m = fmaxf(fmaxf(v.x, v.y), fmaxf(v.z, v.w));
#pragma unroll
    for (int off = 16; off > 0; off >>= 1)
        m = fmaxf(m, __shfl_xor_sync(0xffffffffu, m, off));
    if ((tid & 31) == 0) smem[tid >> 5] = m;
    __syncthreads();
    if (tid == 0)
        g_fmax[pix] = fmaxf(fmaxf(smem[0], smem[1]), fmaxf(smem[2], smem[3]));
}

// K2: one CTA per 12 bins. Phase A: threads 0..11 each compute one bin max
// (bin region <= 8x8 = 64 independent L2 loads). Phase B: each of 256 threads
// writes 6 float4 (12 bins * 512 floats = 1536 float4 = 6*256), coalesced.
__global__ void __launch_bounds__(256) roi_kernel(
    const float* __restrict__ rois, float* __restrict__ out) {
    __shared__ float sbin[BINS_PER_BLK];
    int tid = threadIdx.x;
    int bin0 = blockIdx.x * BINS_PER_BLK;

    if (tid < BINS_PER_BLK) {
        int idx = bin0 + tid;
        int r = idx / NBINS;
        int bin = idx - r * NBINS;
        int i = bin / POOLK;
        int j = bin - i * POOLK;

        const float* roi = rois + r * 5;
        // reference: (rois * (1/16)).astype(int32) -> truncation; inputs >= 0
        int x1 = (int)(__ldg(roi + 1) * 0.0625f);
        int y1 = (int)(__ldg(roi + 2) * 0.0625f);
        int x2 = (int)(__ldg(roi + 3) * 0.0625f);
        int y2 = (int)(__ldg(roi + 4) * 0.0625f);
        int rh = y2 - y1 + 1;
        int rw = x2 - x1 + 1;

        int hs = min(max(y1 + (i * rh) / POOLK, 0), FH);
        int he = min(max(y1 + ((i + 1) * rh + POOLK - 1) / POOLK, 0), FH);
        int ws = min(max(x1 + (j * rw) / POOLK, 0), FW);
        int we = min(max(x1 + ((j + 1) * rw + POOLK - 1) / POOLK, 0), FW);

        float m = -INFINITY;
        for (int y = hs; y < he; y++) {
            const float* row = g_fmax + y * FW;
#pragma unroll 8
            for (int x = ws; x < we; x++)
                m = fmaxf(m, __ldg(row + x));
        }
        sbin[tid] = m;
    }
    __syncthreads();

    // Phase B: float4 index within block's slab = k*256 + tid.
    // local bin = (k*256 + tid) >> 7 = 2k + (tid >> 7).
    int hi = tid >> 7;  // 0 or 1
    float4* o = reinterpret_cast<float4*>(out) +
                (size_t)blockIdx.x * (BINS_PER_BLK * FC / 4);
#pragma unroll
    for (int k = 0; k < 6; k++) {
        float v = sbin[2 * k + hi];
        o[k * 256 + tid] = make_float4(v, v, v, v);
    }
}

extern "C" void kernel_launch(void* const* d_in, const int* in_sizes, int n_in,
                              void* d_out, int out_size) {
    const float* rois = (const float*)d_in[0];          // (300, 5)
    const float* feature_maps = (const float*)d_in[1];  // (50, 50, 512)
    float* out = (float*)d_out;                         // (300, 7, 7, 512)

    fmax_kernel<<<FH * FW, 128>>>(feature_maps);
    roi_kernel<<<(NUM_ROIS * NBINS) / BINS_PER_BLK, 256>>>(rois, out);
}